// round 4
// baseline (speedup 1.0000x reference)
#include <cuda_runtime.h>
#include <cuda_bf16.h>

// Problem constants
#define L_DIM 12
#define B_DIM 4
#define H_DIM 12
#define S_DIM 785
#define NP    784             // S-1, LayerNorm width
#define KSC   588             // kth smallest (1-based)
#define NMAPS (L_DIM * H_DIM) // 144 maps per batch
#define NSPLIT 48             // deterministic partial-sum groups
#define MAPS_PER (NMAPS / NSPLIT) // 3

// Deterministic partial column sums: [batch][split][column]
__device__ float g_partial[B_DIM][NSPLIT][NP];

// ---------------------------------------------------------------------------
// Kernel 1: column-sum reduction over (l, h, i>=1) for columns j=1..784.
// Thread-per-column, row-strided coalesced loads. All 3 maps of this split
// are walked TOGETHER, 4 rows at a time -> 12 independent streaming loads
// in flight per iteration per thread.
// Grid: (4 column-chunks, NSPLIT, B). Block: 256 threads.
// ---------------------------------------------------------------------------
__global__ __launch_bounds__(256) void colsum_kernel(const float* __restrict__ att)
{
    const int chunk = blockIdx.x;           // 0..3  (256 columns each)
    const int split = blockIdx.y;           // 0..NSPLIT-1
    const int b     = blockIdx.z;           // 0..3
    const int j     = chunk * 256 + threadIdx.x + 1;  // column 1..784
    if (j > NP) return;

    const int m0 = split * MAPS_PER;        // 3 consecutive maps
    const size_t SD = (size_t)S_DIM;

    // pointers to att[l][b][h][1][j] for each of the 3 maps
    const float* p0;
    const float* p1;
    const float* p2;
    {
        const int l0 = (m0 + 0) / H_DIM, h0 = (m0 + 0) % H_DIM;
        const int l1 = (m0 + 1) / H_DIM, h1 = (m0 + 1) % H_DIM;
        const int l2 = (m0 + 2) / H_DIM, h2 = (m0 + 2) % H_DIM;
        p0 = att + ((((size_t)l0 * B_DIM + b) * H_DIM + h0) * SD + 1) * SD + j;
        p1 = att + ((((size_t)l1 * B_DIM + b) * H_DIM + h1) * SD + 1) * SD + j;
        p2 = att + ((((size_t)l2 * B_DIM + b) * H_DIM + h2) * SD + 1) * SD + j;
    }

    float a0 = 0.f, a1 = 0.f, a2 = 0.f, a3 = 0.f;
    float a4 = 0.f, a5 = 0.f, a6 = 0.f, a7 = 0.f;
    float a8 = 0.f, a9 = 0.f, aA = 0.f, aB = 0.f;

    // 784 rows, 4 rows x 3 maps = 12 streaming loads per iteration
    #pragma unroll 2
    for (int i = 0; i < NP; i += 4) {
        a0 += __ldcs(p0 + 0 * SD);
        a1 += __ldcs(p1 + 0 * SD);
        a2 += __ldcs(p2 + 0 * SD);
        a3 += __ldcs(p0 + 1 * SD);
        a4 += __ldcs(p1 + 1 * SD);
        a5 += __ldcs(p2 + 1 * SD);
        a6 += __ldcs(p0 + 2 * SD);
        a7 += __ldcs(p1 + 2 * SD);
        a8 += __ldcs(p2 + 2 * SD);
        a9 += __ldcs(p0 + 3 * SD);
        aA += __ldcs(p1 + 3 * SD);
        aB += __ldcs(p2 + 3 * SD);
        p0 += 4 * SD;
        p1 += 4 * SD;
        p2 += 4 * SD;
    }

    g_partial[b][split][j - 1] =
        ((a0 + a1) + (a2 + a3)) + ((a4 + a5) + (a6 + a7)) + ((a8 + a9) + (aA + aB));
}

// ---------------------------------------------------------------------------
// Kernel 2: per-batch finalize. Sum the NSPLIT partials (deterministic order),
// two-pass LayerNorm, sigmoid, kth-smallest threshold via rank counting with
// pipelined broadcast shared reads, write the binary mask.
// Grid: B blocks of NP(=784) threads.
// ---------------------------------------------------------------------------
__global__ void finalize_kernel(const float* __restrict__ gamma,
                                const float* __restrict__ beta,
                                float* __restrict__ out)
{
    const int b   = blockIdx.x;
    const int tid = threadIdx.x;            // 0..783

    __shared__ float red[1024];
    __shared__ float sp[NP];
    __shared__ float sh_thr;

    // deterministic reduction over partials
    float s = 0.f;
    #pragma unroll
    for (int q = 0; q < NSPLIT; ++q)
        s += g_partial[b][q][tid];
    s *= (1.0f / (float)NMAPS);             // mean over heads & layers

    // zero the padding once (indices >= NP stay 0 through both reductions)
    if (tid < 1024 - NP) red[NP + tid] = 0.f;

    // --- pass 1: mean ---
    red[tid] = s;
    __syncthreads();
    for (int st = 512; st > 0; st >>= 1) {
        if (tid < st) red[tid] += red[tid + st];
        __syncthreads();
    }
    const float mean = red[0] * (1.0f / (float)NP);
    __syncthreads();

    // --- pass 2: variance ---
    const float d = s - mean;
    red[tid] = d * d;
    __syncthreads();
    for (int st = 512; st > 0; st >>= 1) {
        if (tid < st) red[tid] += red[tid + st];
        __syncthreads();
    }
    const float var = red[0] * (1.0f / (float)NP);

    // LayerNorm + sigmoid
    const float ln = d * rsqrtf(var + 1e-5f) * gamma[tid] + beta[tid];
    const float pv = 1.0f / (1.0f + expf(-ln));
    sp[tid] = pv;
    __syncthreads();

    // rank-based kth smallest: count strictly-less and equal.
    // Unrolled so the broadcast LDS loads pipeline (batching hides the
    // 29-cycle LDS latency instead of exposing it 784 times serially).
    int cl = 0, ce = 0;
    #pragma unroll 8
    for (int i = 0; i < NP; ++i) {
        const float v = sp[i];
        cl += (v <  pv);
        ce += (v == pv);
    }
    // value at sorted position KSC-1 (0-based)
    if (cl <= (KSC - 1) && (KSC - 1) < cl + ce) sh_thr = pv;
    __syncthreads();

    out[b * NP + tid] = (pv > sh_thr) ? 1.0f : 0.0f;
}

// ---------------------------------------------------------------------------
extern "C" void kernel_launch(void* const* d_in, const int* in_sizes, int n_in,
                              void* d_out, int out_size)
{
    const float* att   = (const float*)d_in[0];
    const float* gamma = (const float*)d_in[1];
    const float* beta  = (const float*)d_in[2];
    float* out = (float*)d_out;

    dim3 grid1(4, NSPLIT, B_DIM);
    colsum_kernel<<<grid1, 256>>>(att);
    finalize_kernel<<<B_DIM, NP>>>(gamma, beta, out);
}

// round 5
// speedup vs baseline: 1.2413x; 1.2413x over previous
#include <cuda_runtime.h>
#include <cuda_bf16.h>

// Problem constants
#define L_DIM 12
#define B_DIM 4
#define H_DIM 12
#define S_DIM 785
#define NP    784             // S-1, LayerNorm width
#define KSC   588             // kth smallest (1-based)
#define NMAPS (L_DIM * H_DIM) // 144 maps per batch

// Deterministic partial column sums: [batch][map][column]
__device__ float g_partial[B_DIM][NMAPS][NP];
// sigmoid(LayerNorm(s)) per batch
__device__ float g_p[B_DIM][NP];
// kth-smallest threshold per batch
__device__ float g_thr[B_DIM];

// ---------------------------------------------------------------------------
// Kernel 1: column sums, row-contiguous streaming.
// One block per (map, batch) streams the whole contiguous [785 x 785] map
// (rows 1..784) sequentially. Positions {t, t+256, t+512, t+768} of a row map
// to the SAME output column j = pos-1 in every row, so each thread keeps 4
// fixed register accumulators while loads are perfectly sequential/coalesced.
// ---------------------------------------------------------------------------
__global__ __launch_bounds__(256) void colsum_kernel(const float* __restrict__ att)
{
    const int m = blockIdx.x;               // 0..143 (l*12+h)
    const int b = blockIdx.y;               // 0..3
    const int l = m / H_DIM;
    const int h = m % H_DIM;
    const int t = threadIdx.x;              // 0..255

    const size_t SD = (size_t)S_DIM;
    const float* p = att + (((size_t)l * B_DIM + b) * H_DIM + h) * SD * SD + SD; // row 1

    const bool has3 = (t + 768) < S_DIM;    // t < 17

    float a0 = 0.f, a1 = 0.f, a2 = 0.f, a3 = 0.f;

    #pragma unroll 4
    for (int i = 0; i < NP; ++i) {
        a0 += __ldcs(p + t);
        a1 += __ldcs(p + t + 256);
        a2 += __ldcs(p + t + 512);
        if (has3) a3 += __ldcs(p + t + 768);
        p += SD;
    }

    // column j = position - 1 (position 0 is the dropped CLS column)
    if (t >= 1)  g_partial[b][m][t - 1]   = a0;
    g_partial[b][m][t + 255] = a1;
    g_partial[b][m][t + 511] = a2;
    if (has3)    g_partial[b][m][t + 767] = a3;   // t<=16 -> j<=783
}

// ---------------------------------------------------------------------------
// Kernel 2: per-batch stats. Deterministic sum over the 144 partials,
// two-pass LayerNorm, sigmoid; store p to global.
// Grid: B blocks of NP(=784) threads.
// ---------------------------------------------------------------------------
__global__ void stats_kernel(const float* __restrict__ gamma,
                             const float* __restrict__ beta)
{
    const int b   = blockIdx.x;
    const int tid = threadIdx.x;            // 0..783

    __shared__ float red[1024];

    float s = 0.f;
    #pragma unroll 8
    for (int q = 0; q < NMAPS; ++q)
        s += g_partial[b][q][tid];
    s *= (1.0f / (float)NMAPS);             // mean over heads & layers

    // zero the padding (indices >= NP stay 0 through both reductions)
    if (tid < 1024 - NP) red[NP + tid] = 0.f;

    // --- pass 1: mean ---
    red[tid] = s;
    __syncthreads();
    for (int st = 512; st > 0; st >>= 1) {
        if (tid < st) red[tid] += red[tid + st];
        __syncthreads();
    }
    const float mean = red[0] * (1.0f / (float)NP);
    __syncthreads();

    // --- pass 2: variance ---
    const float d = s - mean;
    red[tid] = d * d;
    __syncthreads();
    for (int st = 512; st > 0; st >>= 1) {
        if (tid < st) red[tid] += red[tid + st];
        __syncthreads();
    }
    const float var = red[0] * (1.0f / (float)NP);

    const float ln = d * rsqrtf(var + 1e-5f) * gamma[tid] + beta[tid];
    g_p[b][tid] = 1.0f / (1.0f + expf(-ln));
}

// ---------------------------------------------------------------------------
// Kernel 3: kth-smallest threshold via rank counting, distributed over
// 8 blocks per batch (32 blocks total) so the serial 784-iteration count
// loop runs with ~1 warp per scheduler instead of 6 contending.
// The thread owning the rank-(KSC-1) value writes the threshold.
// ---------------------------------------------------------------------------
__global__ __launch_bounds__(128) void rank_kernel()
{
    const int b = blockIdx.y;               // 0..3
    __shared__ float sp[NP];

    for (int i = threadIdx.x; i < NP; i += 128)
        sp[i] = g_p[b][i];
    __syncthreads();

    if (threadIdx.x < 98) {
        const int j = blockIdx.x * 98 + threadIdx.x;   // 0..783
        const float pv = sp[j];
        int cl = 0, ce = 0;
        for (int i = 0; i < NP; ++i) {
            const float v = sp[i];
            cl += (v <  pv);
            ce += (v == pv);
        }
        if (cl <= (KSC - 1) && (KSC - 1) < cl + ce)
            g_thr[b] = pv;                  // ties write the same value
    }
}

// ---------------------------------------------------------------------------
// Kernel 4: elementwise mask.
// ---------------------------------------------------------------------------
__global__ void mask_kernel(float* __restrict__ out)
{
    const int b   = blockIdx.x;
    const int tid = threadIdx.x;
    out[b * NP + tid] = (g_p[b][tid] > g_thr[b]) ? 1.0f : 0.0f;
}

// ---------------------------------------------------------------------------
extern "C" void kernel_launch(void* const* d_in, const int* in_sizes, int n_in,
                              void* d_out, int out_size)
{
    const float* att   = (const float*)d_in[0];
    const float* gamma = (const float*)d_in[1];
    const float* beta  = (const float*)d_in[2];
    float* out = (float*)d_out;

    colsum_kernel<<<dim3(NMAPS, B_DIM), 256>>>(att);
    stats_kernel<<<B_DIM, NP>>>(gamma, beta);
    rank_kernel<<<dim3(8, B_DIM), 128>>>();
    mask_kernel<<<B_DIM, NP>>>(out);
}

// round 8
// speedup vs baseline: 1.4872x; 1.1981x over previous
#include <cuda_runtime.h>
#include <cuda_bf16.h>
#include <cstdint>

// Problem constants
#define L_DIM 12
#define B_DIM 4
#define H_DIM 12
#define S_DIM 785
#define NP    784             // S-1, LayerNorm width
#define KSC   588             // kth smallest (1-based)
#define NMAPS (L_DIM * H_DIM) // 144 maps per batch
#define NGRP  196             // 784 rows / 4 rows per aligned group
#define NELEM (NP * S_DIM)    // 615440 elements streamed per map (rows 1..784)

// Deterministic partial column sums: [batch][map][column]
__device__ float g_partial[B_DIM][NMAPS][NP];
// sigmoid(LayerNorm(s)) per batch
__device__ float g_p[B_DIM][NP];
// kth-smallest threshold per batch
__device__ float g_thr[B_DIM];

// ---------------------------------------------------------------------------
// Kernel 1: column sums via ALIGNED float4 streaming.
// 4 rows = 12560 B = 0 mod 16, so from the first 16B boundary past row 1 the
// map is 196 groups of 785 aligned float4 slots; lane k of slot s hits column
// (phi+4s+k) mod 785 in EVERY group (3140 = 4*785). Each thread owns slots
// {t, t+256, t+512, (+768 if t<17)} with fixed register accumulators.
// phi = 0..3 leading scalars and the group-195 overrun are handled in a peel.
// A 3140-slot shared fold sums the 4 row-phases per column (deterministic).
// Grid: (144 maps, 4 batches), 256 threads.
// ---------------------------------------------------------------------------
__global__ __launch_bounds__(256) void colsum_kernel(const float* __restrict__ att)
{
    const int m = blockIdx.x;               // 0..143 (l*12+h)
    const int b = blockIdx.y;               // 0..3
    const int l = m / H_DIM;
    const int h = m % H_DIM;
    const int t = threadIdx.x;              // 0..255

    const size_t SD = (size_t)S_DIM;
    const float* row1 = att + (((size_t)l * B_DIM + b) * H_DIM + h) * (SD * SD) + SD;

    const int off16 = (int)((uintptr_t)row1 & 15);        // 0,4,8,12
    const int phi   = off16 ? (16 - off16) >> 2 : 0;      // 0..3 leading scalars
    const float4* abase = (const float4*)(row1 + phi);

    float a00=0.f,a01=0.f,a02=0.f,a03=0.f;
    float a10=0.f,a11=0.f,a12=0.f,a13=0.f;
    float a20=0.f,a21=0.f,a22=0.f,a23=0.f;
    float a30=0.f,a31=0.f,a32=0.f,a33=0.f;
    const bool has3 = (t < 17);             // slots 768..784

    const float4* p = abase;
    #pragma unroll 2
    for (int g = 0; g < NGRP - 1; ++g) {    // 195 full groups
        float4 v0 = __ldcs(p + t);
        float4 v1 = __ldcs(p + t + 256);
        float4 v2 = __ldcs(p + t + 512);
        a00+=v0.x; a01+=v0.y; a02+=v0.z; a03+=v0.w;
        a10+=v1.x; a11+=v1.y; a12+=v1.z; a13+=v1.w;
        a20+=v2.x; a21+=v2.y; a22+=v2.z; a23+=v2.w;
        if (has3) {
            float4 v3 = __ldcs(p + t + 768);
            a30+=v3.x; a31+=v3.y; a32+=v3.z; a33+=v3.w;
        }
        p += 785;
    }

    // ---- peel group 195: slot 784's top phi lanes would read past the map;
    // they instead take the phi leading scalars (same (phase,col) slots). ----
    {
        float4 v0 = __ldcs(p + t);
        float4 v1 = __ldcs(p + t + 256);
        float4 v2 = __ldcs(p + t + 512);
        a00+=v0.x; a01+=v0.y; a02+=v0.z; a03+=v0.w;
        a10+=v1.x; a11+=v1.y; a12+=v1.z; a13+=v1.w;
        a20+=v2.x; a21+=v2.y; a22+=v2.z; a23+=v2.w;
        if (t < 16) {
            float4 v3 = __ldcs(p + t + 768);
            a30+=v3.x; a31+=v3.y; a32+=v3.z; a33+=v3.w;
        } else if (t == 16) {
            const float* tail = (const float*)(p + 784);      // elements 615436+phi..
            const float* head = ((const float*)abase) - 4;    // head+k = row1+(k-4+phi)
            float w0 = (0 < 4 - phi) ? tail[0] : head[0];
            float w1 = (1 < 4 - phi) ? tail[1] : head[1];
            float w2 = (2 < 4 - phi) ? tail[2] : head[2];
            float w3 = (3 < 4 - phi) ? tail[3] : head[3];
            a30+=w0; a31+=w1; a32+=w2; a33+=w3;
        }
    }

    // ---- fold the 4 row-phases per column via shared (exclusive slots) ----
    __shared__ float sq[4 * S_DIM];         // 3140 floats
    {
        int q0 = phi + 4 * t;               // < 3140 for all three base slots
        sq[q0+0]=a00; sq[q0+1]=a01; sq[q0+2]=a02; sq[q0+3]=a03;
        int q1 = phi + 4 * (t + 256);
        sq[q1+0]=a10; sq[q1+1]=a11; sq[q1+2]=a12; sq[q1+3]=a13;
        int q2 = phi + 4 * (t + 512);
        sq[q2+0]=a20; sq[q2+1]=a21; sq[q2+2]=a22; sq[q2+3]=a23;
        if (has3) {
            int q3 = phi + 4 * (t + 768);   // may wrap past 3140 for t==16
            int w;
            w = q3+0; if (w >= 4*S_DIM) w -= 4*S_DIM; sq[w]=a30;
            w = q3+1; if (w >= 4*S_DIM) w -= 4*S_DIM; sq[w]=a31;
            w = q3+2; if (w >= 4*S_DIM) w -= 4*S_DIM; sq[w]=a32;
            w = q3+3; if (w >= 4*S_DIM) w -= 4*S_DIM; sq[w]=a33;
        }
    }
    __syncthreads();

    #pragma unroll
    for (int c = t; c < S_DIM; c += 256) {
        if (c == 0) continue;               // CLS column dropped
        float sum = (sq[c] + sq[c + S_DIM]) + (sq[c + 2*S_DIM] + sq[c + 3*S_DIM]);
        g_partial[b][m][c - 1] = sum;
    }
}

// ---------------------------------------------------------------------------
// Kernel 2: per-batch stats. Deterministic sum over the 144 partials,
// two-pass LayerNorm, sigmoid; store p to global.
// Grid: B blocks of NP(=784) threads.
// ---------------------------------------------------------------------------
__global__ void stats_kernel(const float* __restrict__ gamma,
                             const float* __restrict__ beta)
{
    const int b   = blockIdx.x;
    const int tid = threadIdx.x;            // 0..783

    __shared__ float red[1024];

    float s = 0.f;
    #pragma unroll 8
    for (int q = 0; q < NMAPS; ++q)
        s += g_partial[b][q][tid];
    s *= (1.0f / (float)NMAPS);             // mean over heads & layers

    if (tid < 1024 - NP) red[NP + tid] = 0.f;

    // --- pass 1: mean ---
    red[tid] = s;
    __syncthreads();
    for (int st = 512; st > 0; st >>= 1) {
        if (tid < st) red[tid] += red[tid + st];
        __syncthreads();
    }
    const float mean = red[0] * (1.0f / (float)NP);
    __syncthreads();

    // --- pass 2: variance ---
    const float d = s - mean;
    red[tid] = d * d;
    __syncthreads();
    for (int st = 512; st > 0; st >>= 1) {
        if (tid < st) red[tid] += red[tid + st];
        __syncthreads();
    }
    const float var = red[0] * (1.0f / (float)NP);

    const float ln = d * rsqrtf(var + 1e-5f) * gamma[tid] + beta[tid];
    g_p[b][tid] = 1.0f / (1.0f + expf(-ln));
}

// ---------------------------------------------------------------------------
// Kernel 3: kth-smallest threshold via rank counting, 8 blocks per batch.
// ---------------------------------------------------------------------------
__global__ __launch_bounds__(128) void rank_kernel()
{
    const int b = blockIdx.y;               // 0..3
    __shared__ float sp[NP];

    for (int i = threadIdx.x; i < NP; i += 128)
        sp[i] = g_p[b][i];
    __syncthreads();

    if (threadIdx.x < 98) {
        const int j = blockIdx.x * 98 + threadIdx.x;   // 0..783
        const float pv = sp[j];
        int cl = 0, ce = 0;
        for (int i = 0; i < NP; ++i) {
            const float v = sp[i];
            cl += (v <  pv);
            ce += (v == pv);
        }
        if (cl <= (KSC - 1) && (KSC - 1) < cl + ce)
            g_thr[b] = pv;                  // ties write the same value
    }
}

// ---------------------------------------------------------------------------
// Kernel 4: elementwise mask.
// ---------------------------------------------------------------------------
__global__ void mask_kernel(float* __restrict__ out)
{
    const int b   = blockIdx.x;
    const int tid = threadIdx.x;
    out[b * NP + tid] = (g_p[b][tid] > g_thr[b]) ? 1.0f : 0.0f;
}

// ---------------------------------------------------------------------------
extern "C" void kernel_launch(void* const* d_in, const int* in_sizes, int n_in,
                              void* d_out, int out_size)
{
    const float* att   = (const float*)d_in[0];
    const float* gamma = (const float*)d_in[1];
    const float* beta  = (const float*)d_in[2];
    float* out = (float*)d_out;

    colsum_kernel<<<dim3(NMAPS, B_DIM), 256>>>(att);
    stats_kernel<<<B_DIM, NP>>>(gamma, beta);
    rank_kernel<<<dim3(8, B_DIM), 128>>>();
    mask_kernel<<<B_DIM, NP>>>(out);
}

// round 9
// speedup vs baseline: 1.5317x; 1.0300x over previous
#include <cuda_runtime.h>
#include <cuda_bf16.h>
#include <cstdint>

// Problem constants
#define L_DIM 12
#define B_DIM 4
#define H_DIM 12
#define S_DIM 785
#define NP    784             // S-1, LayerNorm width
#define KSC   588             // kth smallest (1-based)
#define NMAPS (L_DIM * H_DIM) // 144 maps per batch
#define NGRP  196             // 784 rows / 4 rows per aligned group

// Deterministic partial column sums: [batch][map][column]
__device__ float g_partial[B_DIM][NMAPS][NP];

// ---------------------------------------------------------------------------
// Kernel 1: column sums via ALIGNED float4 streaming (unchanged from R8 win).
// ---------------------------------------------------------------------------
__global__ __launch_bounds__(256) void colsum_kernel(const float* __restrict__ att)
{
    const int m = blockIdx.x;               // 0..143 (l*12+h)
    const int b = blockIdx.y;               // 0..3
    const int l = m / H_DIM;
    const int h = m % H_DIM;
    const int t = threadIdx.x;              // 0..255

    const size_t SD = (size_t)S_DIM;
    const float* row1 = att + (((size_t)l * B_DIM + b) * H_DIM + h) * (SD * SD) + SD;

    const int off16 = (int)((uintptr_t)row1 & 15);        // 0,4,8,12
    const int phi   = off16 ? (16 - off16) >> 2 : 0;      // 0..3 leading scalars
    const float4* abase = (const float4*)(row1 + phi);

    float a00=0.f,a01=0.f,a02=0.f,a03=0.f;
    float a10=0.f,a11=0.f,a12=0.f,a13=0.f;
    float a20=0.f,a21=0.f,a22=0.f,a23=0.f;
    float a30=0.f,a31=0.f,a32=0.f,a33=0.f;
    const bool has3 = (t < 17);             // slots 768..784

    const float4* p = abase;
    #pragma unroll 2
    for (int g = 0; g < NGRP - 1; ++g) {    // 195 full groups
        float4 v0 = __ldcs(p + t);
        float4 v1 = __ldcs(p + t + 256);
        float4 v2 = __ldcs(p + t + 512);
        a00+=v0.x; a01+=v0.y; a02+=v0.z; a03+=v0.w;
        a10+=v1.x; a11+=v1.y; a12+=v1.z; a13+=v1.w;
        a20+=v2.x; a21+=v2.y; a22+=v2.z; a23+=v2.w;
        if (has3) {
            float4 v3 = __ldcs(p + t + 768);
            a30+=v3.x; a31+=v3.y; a32+=v3.z; a33+=v3.w;
        }
        p += 785;
    }

    // ---- peel group 195: slot 784's top phi lanes would read past the map;
    // they instead take the phi leading scalars (same (phase,col) slots). ----
    {
        float4 v0 = __ldcs(p + t);
        float4 v1 = __ldcs(p + t + 256);
        float4 v2 = __ldcs(p + t + 512);
        a00+=v0.x; a01+=v0.y; a02+=v0.z; a03+=v0.w;
        a10+=v1.x; a11+=v1.y; a12+=v1.z; a13+=v1.w;
        a20+=v2.x; a21+=v2.y; a22+=v2.z; a23+=v2.w;
        if (t < 16) {
            float4 v3 = __ldcs(p + t + 768);
            a30+=v3.x; a31+=v3.y; a32+=v3.z; a33+=v3.w;
        } else if (t == 16) {
            const float* tail = (const float*)(p + 784);
            const float* head = ((const float*)abase) - 4;
            float w0 = (0 < 4 - phi) ? tail[0] : head[0];
            float w1 = (1 < 4 - phi) ? tail[1] : head[1];
            float w2 = (2 < 4 - phi) ? tail[2] : head[2];
            float w3 = (3 < 4 - phi) ? tail[3] : head[3];
            a30+=w0; a31+=w1; a32+=w2; a33+=w3;
        }
    }

    // ---- fold the 4 row-phases per column via shared (exclusive slots) ----
    __shared__ float sq[4 * S_DIM];         // 3140 floats
    {
        int q0 = phi + 4 * t;
        sq[q0+0]=a00; sq[q0+1]=a01; sq[q0+2]=a02; sq[q0+3]=a03;
        int q1 = phi + 4 * (t + 256);
        sq[q1+0]=a10; sq[q1+1]=a11; sq[q1+2]=a12; sq[q1+3]=a13;
        int q2 = phi + 4 * (t + 512);
        sq[q2+0]=a20; sq[q2+1]=a21; sq[q2+2]=a22; sq[q2+3]=a23;
        if (has3) {
            int q3 = phi + 4 * (t + 768);   // may wrap past 3140 for t==16
            int w;
            w = q3+0; if (w >= 4*S_DIM) w -= 4*S_DIM; sq[w]=a30;
            w = q3+1; if (w >= 4*S_DIM) w -= 4*S_DIM; sq[w]=a31;
            w = q3+2; if (w >= 4*S_DIM) w -= 4*S_DIM; sq[w]=a32;
            w = q3+3; if (w >= 4*S_DIM) w -= 4*S_DIM; sq[w]=a33;
        }
    }
    __syncthreads();

    #pragma unroll
    for (int c = t; c < S_DIM; c += 256) {
        if (c == 0) continue;               // CLS column dropped
        float sum = (sq[c] + sq[c + S_DIM]) + (sq[c + 2*S_DIM] + sq[c + 3*S_DIM]);
        g_partial[b][m][c - 1] = sum;
    }
}

// ---------------------------------------------------------------------------
// Kernel 2: fused epilogue. Grid B x 800 threads (25 full warps; threads
// 784..799 are inert padding so every __ballot_sync uses the full mask).
//   1) deterministic sum of 144 partials, LayerNorm (two shared-tree passes)
//   2) p = sigmoid(ln)
//   3) kth-smallest via 31-step bisection on the float BIT pattern
//      (p > 0, and positive IEEE floats are monotone in uint bits, so the
//      smallest v with count(bits<=v) >= KSC is EXACTLY sort(p)[KSC-1])
//   4) mask write with the block-uniform threshold
// ---------------------------------------------------------------------------
#define EPI_T 800
#define EPI_W (EPI_T / 32)   // 25 warps

__global__ __launch_bounds__(EPI_T) void epilogue_kernel(const float* __restrict__ gamma,
                                                         const float* __restrict__ beta,
                                                         float* __restrict__ out)
{
    const int b    = blockIdx.x;
    const int tid  = threadIdx.x;           // 0..799
    const int lane = tid & 31;
    const int wid  = tid >> 5;
    const bool act = (tid < NP);

    __shared__ float red[1024];
    __shared__ int   wcnt[EPI_W];
    __shared__ int   sh_total;

    // ---- deterministic reduction over the 144 partials ----
    float s = 0.f;
    if (act) {
        #pragma unroll 8
        for (int q = 0; q < NMAPS; ++q)
            s += g_partial[b][q][tid];
        s *= (1.0f / (float)NMAPS);
    }

    // zero padding region of the tree
    if (tid >= NP) { red[tid] = 0.f; if (tid + (1024 - EPI_T) < 1024 && tid == NP) {} }
    if (tid < 1024 - EPI_T) red[EPI_T + tid] = 0.f;

    // --- pass 1: mean ---
    if (act) red[tid] = s;
    __syncthreads();
    for (int st = 512; st > 0; st >>= 1) {
        if (tid < st) red[tid] += red[tid + st];
        __syncthreads();
    }
    const float mean = red[0] * (1.0f / (float)NP);
    __syncthreads();

    // --- pass 2: variance ---
    const float d = act ? (s - mean) : 0.f;
    red[tid] = d * d;
    __syncthreads();
    for (int st = 512; st > 0; st >>= 1) {
        if (tid < st) red[tid] += red[tid + st];
        __syncthreads();
    }
    const float var = red[0] * (1.0f / (float)NP);
    __syncthreads();

    // ---- LayerNorm + sigmoid ----
    float pv = 0.f;
    unsigned pb = 0x7F800000u;              // +inf for padding: never counted
    if (act) {
        const float ln = d * rsqrtf(var + 1e-5f) * gamma[tid] + beta[tid];
        pv = 1.0f / (1.0f + expf(-ln));
        pb = __float_as_uint(pv);           // positive -> monotone bits
    }

    // ---- bisection on bit pattern: smallest v with count(pb<=v) >= KSC ----
    unsigned lo = 0u, hi = 0x3F800000u;     // p in (0, 1.0]; hi covers p==1.0
    while (lo < hi) {                       // uniform across block (~31 iters)
        const unsigned mid = (lo + hi) >> 1;
        const unsigned bal = __ballot_sync(0xFFFFFFFFu, pb <= mid);
        if (lane == 0) wcnt[wid] = __popc(bal);
        __syncthreads();
        if (wid == 0) {
            int v = (lane < EPI_W) ? wcnt[lane] : 0;
            #pragma unroll
            for (int o = 16; o > 0; o >>= 1) v += __shfl_down_sync(0xFFFFFFFFu, v, o);
            if (lane == 0) sh_total = v;
        }
        __syncthreads();
        if (sh_total >= KSC) hi = mid; else lo = mid + 1;
        __syncthreads();                    // protect sh_total before next write
    }
    const float thr = __uint_as_float(lo);  // == sort(p)[KSC-1], bit-exact

    // ---- mask ----
    if (act)
        out[b * NP + tid] = (pv > thr) ? 1.0f : 0.0f;
}

// ---------------------------------------------------------------------------
extern "C" void kernel_launch(void* const* d_in, const int* in_sizes, int n_in,
                              void* d_out, int out_size)
{
    const float* att   = (const float*)d_in[0];
    const float* gamma = (const float*)d_in[1];
    const float* beta  = (const float*)d_in[2];
    float* out = (float*)d_out;

    colsum_kernel<<<dim3(NMAPS, B_DIM), 256>>>(att);
    epilogue_kernel<<<B_DIM, EPI_T>>>(gamma, beta, out);
}

// round 11
// speedup vs baseline: 1.5319x; 1.0001x over previous
#include <cuda_runtime.h>
#include <cuda_bf16.h>
#include <cstdint>

// Problem constants
#define L_DIM 12
#define B_DIM 4
#define H_DIM 12
#define S_DIM 785
#define NP    784             // S-1, LayerNorm width
#define KSC   588             // kth smallest (1-based)
#define NMAPS (L_DIM * H_DIM) // 144 maps per batch
#define NGRP  196             // 784 rows / 4 rows per aligned group

// Deterministic partial column sums: [batch][map][column]
__device__ float g_partial[B_DIM][NMAPS][NP];
// Reduced column means: [batch][column]
__device__ float g_s[B_DIM][NP];

// ---------------------------------------------------------------------------
// Kernel 1: column sums via ALIGNED float4 streaming (unchanged — at the
// DRAM/LTS ceiling, ~6.9 TB/s).
// ---------------------------------------------------------------------------
__global__ __launch_bounds__(256) void colsum_kernel(const float* __restrict__ att)
{
    const int m = blockIdx.x;               // 0..143 (l*12+h)
    const int b = blockIdx.y;               // 0..3
    const int l = m / H_DIM;
    const int h = m % H_DIM;
    const int t = threadIdx.x;              // 0..255

    const size_t SD = (size_t)S_DIM;
    const float* row1 = att + (((size_t)l * B_DIM + b) * H_DIM + h) * (SD * SD) + SD;

    const int off16 = (int)((uintptr_t)row1 & 15);        // 0,4,8,12
    const int phi   = off16 ? (16 - off16) >> 2 : 0;      // 0..3 leading scalars
    const float4* abase = (const float4*)(row1 + phi);

    float a00=0.f,a01=0.f,a02=0.f,a03=0.f;
    float a10=0.f,a11=0.f,a12=0.f,a13=0.f;
    float a20=0.f,a21=0.f,a22=0.f,a23=0.f;
    float a30=0.f,a31=0.f,a32=0.f,a33=0.f;
    const bool has3 = (t < 17);             // slots 768..784

    const float4* p = abase;
    #pragma unroll 2
    for (int g = 0; g < NGRP - 1; ++g) {    // 195 full groups
        float4 v0 = __ldcs(p + t);
        float4 v1 = __ldcs(p + t + 256);
        float4 v2 = __ldcs(p + t + 512);
        a00+=v0.x; a01+=v0.y; a02+=v0.z; a03+=v0.w;
        a10+=v1.x; a11+=v1.y; a12+=v1.z; a13+=v1.w;
        a20+=v2.x; a21+=v2.y; a22+=v2.z; a23+=v2.w;
        if (has3) {
            float4 v3 = __ldcs(p + t + 768);
            a30+=v3.x; a31+=v3.y; a32+=v3.z; a33+=v3.w;
        }
        p += 785;
    }

    // ---- peel group 195 ----
    {
        float4 v0 = __ldcs(p + t);
        float4 v1 = __ldcs(p + t + 256);
        float4 v2 = __ldcs(p + t + 512);
        a00+=v0.x; a01+=v0.y; a02+=v0.z; a03+=v0.w;
        a10+=v1.x; a11+=v1.y; a12+=v1.z; a13+=v1.w;
        a20+=v2.x; a21+=v2.y; a22+=v2.z; a23+=v2.w;
        if (t < 16) {
            float4 v3 = __ldcs(p + t + 768);
            a30+=v3.x; a31+=v3.y; a32+=v3.z; a33+=v3.w;
        } else if (t == 16) {
            const float* tail = (const float*)(p + 784);
            const float* head = ((const float*)abase) - 4;
            float w0 = (0 < 4 - phi) ? tail[0] : head[0];
            float w1 = (1 < 4 - phi) ? tail[1] : head[1];
            float w2 = (2 < 4 - phi) ? tail[2] : head[2];
            float w3 = (3 < 4 - phi) ? tail[3] : head[3];
            a30+=w0; a31+=w1; a32+=w2; a33+=w3;
        }
    }

    // ---- fold the 4 row-phases per column via shared (exclusive slots) ----
    __shared__ float sq[4 * S_DIM];         // 3140 floats
    {
        int q0 = phi + 4 * t;
        sq[q0+0]=a00; sq[q0+1]=a01; sq[q0+2]=a02; sq[q0+3]=a03;
        int q1 = phi + 4 * (t + 256);
        sq[q1+0]=a10; sq[q1+1]=a11; sq[q1+2]=a12; sq[q1+3]=a13;
        int q2 = phi + 4 * (t + 512);
        sq[q2+0]=a20; sq[q2+1]=a21; sq[q2+2]=a22; sq[q2+3]=a23;
        if (has3) {
            int q3 = phi + 4 * (t + 768);   // may wrap past 3140 for t==16
            int w;
            w = q3+0; if (w >= 4*S_DIM) w -= 4*S_DIM; sq[w]=a30;
            w = q3+1; if (w >= 4*S_DIM) w -= 4*S_DIM; sq[w]=a31;
            w = q3+2; if (w >= 4*S_DIM) w -= 4*S_DIM; sq[w]=a32;
            w = q3+3; if (w >= 4*S_DIM) w -= 4*S_DIM; sq[w]=a33;
        }
    }
    __syncthreads();

    #pragma unroll
    for (int c = t; c < S_DIM; c += 256) {
        if (c == 0) continue;               // CLS column dropped
        float sum = (sq[c] + sq[c + S_DIM]) + (sq[c + 2*S_DIM] + sq[c + 3*S_DIM]);
        g_partial[b][m][c - 1] = sum;
    }
}

// ---------------------------------------------------------------------------
// Kernel 2: partial-matrix reduction, SPREAD over 64 blocks (the 1.77 MB
// g_partial load was the R9 bottleneck at grid=4: per-SM load throughput
// ~20 GB/s caps a 4-block kernel at ~80 GB/s). Deterministic order.
// Grid (16, B), 64 threads; block x covers 49 columns.
// ---------------------------------------------------------------------------
__global__ __launch_bounds__(64) void reduce_kernel()
{
    const int b = blockIdx.y;
    const int j = blockIdx.x * 49 + threadIdx.x;   // 0..783
    if (threadIdx.x >= 49) return;

    float s = 0.f;
    #pragma unroll 8
    for (int q = 0; q < NMAPS; ++q)
        s += g_partial[b][q][j];
    g_s[b][j] = s * (1.0f / (float)NMAPS);
}

// ---------------------------------------------------------------------------
// Kernel 3: fused LayerNorm + sigmoid + exact kth-smallest (bit bisection)
// + mask. Grid B x 800 threads (25 full warps; 784..799 inert padding).
// Bisection uses parity double-buffered counters: 2 __syncthreads per iter.
// ---------------------------------------------------------------------------
#define EPI_T 800
#define EPI_W (EPI_T / 32)   // 25 warps

__global__ __launch_bounds__(EPI_T) void epilogue_kernel(const float* __restrict__ gamma,
                                                         const float* __restrict__ beta,
                                                         float* __restrict__ out)
{
    const int b    = blockIdx.x;
    const int tid  = threadIdx.x;           // 0..799
    const int lane = tid & 31;
    const int wid  = tid >> 5;
    const bool act = (tid < NP);

    __shared__ float red[1024];
    __shared__ int   wcnt[2][EPI_W];
    __shared__ int   sh_total[2];

    const float s = act ? g_s[b][tid] : 0.f;

    // zero padding region of the tree
    if (tid >= NP) red[tid] = 0.f;
    if (tid < 1024 - EPI_T) red[EPI_T + tid] = 0.f;

    // --- pass 1: mean ---
    if (act) red[tid] = s;
    __syncthreads();
    for (int st = 512; st > 0; st >>= 1) {
        if (tid < st) red[tid] += red[tid + st];
        __syncthreads();
    }
    const float mean = red[0] * (1.0f / (float)NP);
    __syncthreads();

    // --- pass 2: variance ---
    const float d = act ? (s - mean) : 0.f;
    red[tid] = d * d;
    __syncthreads();
    for (int st = 512; st > 0; st >>= 1) {
        if (tid < st) red[tid] += red[tid + st];
        __syncthreads();
    }
    const float var = red[0] * (1.0f / (float)NP);

    // ---- LayerNorm + sigmoid ----
    float pv = 0.f;
    unsigned pb = 0x7F800000u;              // +inf for padding: never counted
    if (act) {
        const float ln = d * rsqrtf(var + 1e-5f) * gamma[tid] + beta[tid];
        pv = 1.0f / (1.0f + expf(-ln));
        pb = __float_as_uint(pv);           // positive -> monotone bits
    }
    __syncthreads();                        // red reads done before reuse-free loop

    // ---- bisection on bit pattern: smallest v with count(pb<=v) >= KSC ----
    // Exactly sort(p)[KSC-1] since positive floats are bit-monotone.
    unsigned lo = 0u, hi = 0x3F800000u;     // p in (0, 1.0]
    int par = 0;
    while (lo < hi) {                       // uniform across block (~31 iters)
        const unsigned mid = (lo + hi) >> 1;
        const unsigned bal = __ballot_sync(0xFFFFFFFFu, pb <= mid);
        if (lane == 0) wcnt[par][wid] = __popc(bal);
        __syncthreads();
        if (wid == 0) {
            int v = (lane < EPI_W) ? wcnt[par][lane] : 0;
            #pragma unroll
            for (int o = 16; o > 0; o >>= 1) v += __shfl_down_sync(0xFFFFFFFFu, v, o);
            if (lane == 0) sh_total[par] = v;
        }
        __syncthreads();
        if (sh_total[par] >= KSC) hi = mid; else lo = mid + 1;
        par ^= 1;                           // next iter writes the other slot
    }
    const float thr = __uint_as_float(lo);  // == sort(p)[KSC-1], bit-exact

    // ---- mask ----
    if (act)
        out[b * NP + tid] = (pv > thr) ? 1.0f : 0.0f;
}

// ---------------------------------------------------------------------------
extern "C" void kernel_launch(void* const* d_in, const int* in_sizes, int n_in,
                              void* d_out, int out_size)
{
    const float* att   = (const float*)d_in[0];
    const float* gamma = (const float*)d_in[1];
    const float* beta  = (const float*)d_in[2];
    float* out = (float*)d_out;

    colsum_kernel<<<dim3(NMAPS, B_DIM), 256>>>(att);
    reduce_kernel<<<dim3(16, B_DIM), 64>>>();
    epilogue_kernel<<<B_DIM, EPI_T>>>(gamma, beta, out);
}

// round 13
// speedup vs baseline: 1.5456x; 1.0089x over previous
#include <cuda_runtime.h>
#include <cuda_bf16.h>
#include <cstdint>

// Problem constants
#define L_DIM 12
#define B_DIM 4
#define H_DIM 12
#define S_DIM 785
#define NP    784             // S-1, LayerNorm width
#define KSC   588             // kth smallest (1-based)
#define NMAPS (L_DIM * H_DIM) // 144 maps per batch
#define NGRP  196             // 784 rows / 4 rows per aligned group

// Deterministic partial column sums: [batch][map][column]
__device__ float g_partial[B_DIM][NMAPS][NP];
// Reduced column means: [batch][column]
__device__ float g_s[B_DIM][NP];

// ---------------------------------------------------------------------------
// Kernel 1: column sums via ALIGNED float4 streaming.
// UNCHANGED from the R8/R11 win: measured 85.2% DRAM, 6752 GB/s — at the
// practical HBM read ceiling; do not touch.
// ---------------------------------------------------------------------------
__global__ __launch_bounds__(256) void colsum_kernel(const float* __restrict__ att)
{
    const int m = blockIdx.x;               // 0..143 (l*12+h)
    const int b = blockIdx.y;               // 0..3
    const int l = m / H_DIM;
    const int h = m % H_DIM;
    const int t = threadIdx.x;              // 0..255

    const size_t SD = (size_t)S_DIM;
    const float* row1 = att + (((size_t)l * B_DIM + b) * H_DIM + h) * (SD * SD) + SD;

    const int off16 = (int)((uintptr_t)row1 & 15);        // 0,4,8,12
    const int phi   = off16 ? (16 - off16) >> 2 : 0;      // 0..3 leading scalars
    const float4* abase = (const float4*)(row1 + phi);

    float a00=0.f,a01=0.f,a02=0.f,a03=0.f;
    float a10=0.f,a11=0.f,a12=0.f,a13=0.f;
    float a20=0.f,a21=0.f,a22=0.f,a23=0.f;
    float a30=0.f,a31=0.f,a32=0.f,a33=0.f;
    const bool has3 = (t < 17);             // slots 768..784

    const float4* p = abase;
    #pragma unroll 2
    for (int g = 0; g < NGRP - 1; ++g) {    // 195 full groups
        float4 v0 = __ldcs(p + t);
        float4 v1 = __ldcs(p + t + 256);
        float4 v2 = __ldcs(p + t + 512);
        a00+=v0.x; a01+=v0.y; a02+=v0.z; a03+=v0.w;
        a10+=v1.x; a11+=v1.y; a12+=v1.z; a13+=v1.w;
        a20+=v2.x; a21+=v2.y; a22+=v2.z; a23+=v2.w;
        if (has3) {
            float4 v3 = __ldcs(p + t + 768);
            a30+=v3.x; a31+=v3.y; a32+=v3.z; a33+=v3.w;
        }
        p += 785;
    }

    // ---- peel group 195 ----
    {
        float4 v0 = __ldcs(p + t);
        float4 v1 = __ldcs(p + t + 256);
        float4 v2 = __ldcs(p + t + 512);
        a00+=v0.x; a01+=v0.y; a02+=v0.z; a03+=v0.w;
        a10+=v1.x; a11+=v1.y; a12+=v1.z; a13+=v1.w;
        a20+=v2.x; a21+=v2.y; a22+=v2.z; a23+=v2.w;
        if (t < 16) {
            float4 v3 = __ldcs(p + t + 768);
            a30+=v3.x; a31+=v3.y; a32+=v3.z; a33+=v3.w;
        } else if (t == 16) {
            const float* tail = (const float*)(p + 784);
            const float* head = ((const float*)abase) - 4;
            float w0 = (0 < 4 - phi) ? tail[0] : head[0];
            float w1 = (1 < 4 - phi) ? tail[1] : head[1];
            float w2 = (2 < 4 - phi) ? tail[2] : head[2];
            float w3 = (3 < 4 - phi) ? tail[3] : head[3];
            a30+=w0; a31+=w1; a32+=w2; a33+=w3;
        }
    }

    // ---- fold the 4 row-phases per column via shared (exclusive slots) ----
    __shared__ float sq[4 * S_DIM];         // 3140 floats
    {
        int q0 = phi + 4 * t;
        sq[q0+0]=a00; sq[q0+1]=a01; sq[q0+2]=a02; sq[q0+3]=a03;
        int q1 = phi + 4 * (t + 256);
        sq[q1+0]=a10; sq[q1+1]=a11; sq[q1+2]=a12; sq[q1+3]=a13;
        int q2 = phi + 4 * (t + 512);
        sq[q2+0]=a20; sq[q2+1]=a21; sq[q2+2]=a22; sq[q2+3]=a23;
        if (has3) {
            int q3 = phi + 4 * (t + 768);   // may wrap past 3140 for t==16
            int w;
            w = q3+0; if (w >= 4*S_DIM) w -= 4*S_DIM; sq[w]=a30;
            w = q3+1; if (w >= 4*S_DIM) w -= 4*S_DIM; sq[w]=a31;
            w = q3+2; if (w >= 4*S_DIM) w -= 4*S_DIM; sq[w]=a32;
            w = q3+3; if (w >= 4*S_DIM) w -= 4*S_DIM; sq[w]=a33;
        }
    }
    __syncthreads();

    #pragma unroll
    for (int c = t; c < S_DIM; c += 256) {
        if (c == 0) continue;               // CLS column dropped
        float sum = (sq[c] + sq[c + S_DIM]) + (sq[c + 2*S_DIM] + sq[c + 3*S_DIM]);
        g_partial[b][m][c - 1] = sum;
    }
}

// ---------------------------------------------------------------------------
// Kernel 2: partial-matrix reduction spread over 32 blocks, all threads
// active (98 per block; 8 x 98 = 784 columns). Deterministic order, 16-deep
// independent accumulation for latency hiding (loads hit the freshly-written
// L2 lines).
// ---------------------------------------------------------------------------
__global__ __launch_bounds__(98) void reduce_kernel()
{
    const int b = blockIdx.y;
    const int j = blockIdx.x * 98 + threadIdx.x;   // 0..783

    float s = 0.f;
    #pragma unroll 16
    for (int q = 0; q < NMAPS; ++q)
        s += g_partial[b][q][j];
    g_s[b][j] = s * (1.0f / (float)NMAPS);
}

// ---------------------------------------------------------------------------
// Kernel 3: fused LayerNorm + sigmoid + exact kth-smallest + mask.
// The kth-smallest bisection now uses __syncthreads_count (BAR.RED.POPC):
// one hardware barrier returns the block-wide rank count per iteration —
// no ballot/shared/tree, ~30 barriers total instead of ~93.
// Grid B x 800 threads (784..799 inert padding, pb=+inf never counted).
// ---------------------------------------------------------------------------
#define EPI_T 800

__global__ __launch_bounds__(EPI_T) void epilogue_kernel(const float* __restrict__ gamma,
                                                         const float* __restrict__ beta,
                                                         float* __restrict__ out)
{
    const int b   = blockIdx.x;
    const int tid = threadIdx.x;            // 0..799
    const bool act = (tid < NP);

    __shared__ float red[1024];

    const float s = act ? g_s[b][tid] : 0.f;

    // zero padding region of the tree
    if (tid >= NP) red[tid] = 0.f;
    if (tid < 1024 - EPI_T) red[EPI_T + tid] = 0.f;

    // --- pass 1: mean ---
    if (act) red[tid] = s;
    __syncthreads();
    for (int st = 512; st > 0; st >>= 1) {
        if (tid < st) red[tid] += red[tid + st];
        __syncthreads();
    }
    const float mean = red[0] * (1.0f / (float)NP);
    __syncthreads();

    // --- pass 2: variance ---
    const float d = act ? (s - mean) : 0.f;
    red[tid] = d * d;
    __syncthreads();
    for (int st = 512; st > 0; st >>= 1) {
        if (tid < st) red[tid] += red[tid + st];
        __syncthreads();
    }
    const float var = red[0] * (1.0f / (float)NP);

    // ---- LayerNorm + sigmoid ----
    float pv = 0.f;
    unsigned pb = 0x7F800000u;              // +inf for padding: never counted
    if (act) {
        const float ln = d * rsqrtf(var + 1e-5f) * gamma[tid] + beta[tid];
        pv = 1.0f / (1.0f + expf(-ln));
        pb = __float_as_uint(pv);           // positive -> monotone bits
    }

    // ---- bisection on bit pattern: smallest v with count(pb<=v) >= KSC ----
    // Exactly sort(p)[KSC-1]: positive IEEE floats are monotone in uint bits.
    // One __syncthreads_count (hardware BAR.RED.POPC) per iteration.
    unsigned lo = 0u, hi = 0x3F800000u;     // p in (0, 1.0]
    while (lo < hi) {                       // ~30 uniform iterations
        const unsigned mid = (lo + hi) >> 1;
        const int cnt = __syncthreads_count(pb <= mid);
        if (cnt >= KSC) hi = mid; else lo = mid + 1;
    }
    const float thr = __uint_as_float(lo);  // == sort(p)[KSC-1], bit-exact

    // ---- mask ----
    if (act)
        out[b * NP + tid] = (pv > thr) ? 1.0f : 0.0f;
}

// ---------------------------------------------------------------------------
extern "C" void kernel_launch(void* const* d_in, const int* in_sizes, int n_in,
                              void* d_out, int out_size)
{
    const float* att   = (const float*)d_in[0];
    const float* gamma = (const float*)d_in[1];
    const float* beta  = (const float*)d_in[2];
    float* out = (float*)d_out;

    colsum_kernel<<<dim3(NMAPS, B_DIM), 256>>>(att);
    reduce_kernel<<<dim3(8, B_DIM), 98>>>();
    epilogue_kernel<<<B_DIM, EPI_T>>>(gamma, beta, out);
}